// round 1
// baseline (speedup 1.0000x reference)
#include <cuda_runtime.h>
#include <cuda_bf16.h>
#include <math.h>

// ---------------- problem constants ----------------
#define HEADS   24
#define HDIM    128
#define DIM     3072          // HEADS * HDIM
#define S_TXT   512
#define S_IMG   2048
#define S_TOT   2560          // S_TXT + S_IMG
#define EPS     1e-5f
#define QK_SCALE 0.08838834764831845f   // 1/sqrt(128)

// ---------------- scratch (device globals; allocation-free) ----------------
__device__ float g_q[(size_t)S_TOT * DIM];
__device__ float g_k[(size_t)S_TOT * DIM];
__device__ float g_v[(size_t)S_TOT * DIM];
__device__ float g_o[(size_t)S_TOT * DIM];
__device__ float g_s[(size_t)HEADS * S_TOT * S_TOT];   // attention scores/probs

// ---------------- generic 128x128x8 SGEMM ----------------
// NT = true :  C[m,n] = scale * sum_k A[m,k] * B[n,k]   (+ bias[n])
// NT = false:  C[m,n] = scale * sum_k A[m,k] * B[k,n]   (+ bias[n])
// batched over blockIdx.z with element strides sA/sB/sC.
// Requires: M%128==0, N%128==0, K%8==0, all row strides %4==0, 16B-aligned bases.
template<bool NT>
__global__ void __launch_bounds__(256)
gemm_k(const float* __restrict__ A, const float* __restrict__ B,
       const float* __restrict__ bias, float* __restrict__ C,
       int M, int N, int K, int lda, int ldb, int ldc,
       long long sA, long long sB, long long sC, float scale)
{
    __shared__ float As[8][128];
    __shared__ float Bs[8][128];

    A += (size_t)blockIdx.z * sA;
    B += (size_t)blockIdx.z * sB;
    C += (size_t)blockIdx.z * sC;

    const int row0 = blockIdx.y * 128;
    const int col0 = blockIdx.x * 128;
    const int tid  = threadIdx.x;
    const int tx   = tid & 15;     // 0..15 -> n
    const int ty   = tid >> 4;     // 0..15 -> m

    float acc[8][8];
#pragma unroll
    for (int i = 0; i < 8; i++)
#pragma unroll
        for (int j = 0; j < 8; j++) acc[i][j] = 0.f;

    // load index precompute
    const int ia  = tid * 4;
    const int a_m = ia >> 3;        // 0..127
    const int a_k = ia & 7;         // 0 or 4

    for (int k0 = 0; k0 < K; k0 += 8) {
        // ---- A tile: As[k][m] = A[row0+m, k0+k]
        {
            float4 v = *reinterpret_cast<const float4*>(
                &A[(size_t)(row0 + a_m) * lda + k0 + a_k]);
            As[a_k + 0][a_m] = v.x;
            As[a_k + 1][a_m] = v.y;
            As[a_k + 2][a_m] = v.z;
            As[a_k + 3][a_m] = v.w;
        }
        // ---- B tile
        if (NT) {
            // Bs[k][n] = B[col0+n, k0+k]
            float4 v = *reinterpret_cast<const float4*>(
                &B[(size_t)(col0 + a_m) * ldb + k0 + a_k]);
            Bs[a_k + 0][a_m] = v.x;
            Bs[a_k + 1][a_m] = v.y;
            Bs[a_k + 2][a_m] = v.z;
            Bs[a_k + 3][a_m] = v.w;
        } else {
            // Bs[k][n] = B[k0+k, col0+n]  (coalesced float4 along n)
            const int b_k = ia >> 7;     // 0..7
            const int b_n = ia & 127;    // multiple of 4
            float4 v = *reinterpret_cast<const float4*>(
                &B[(size_t)(k0 + b_k) * ldb + col0 + b_n]);
            *reinterpret_cast<float4*>(&Bs[b_k][b_n]) = v;
        }
        __syncthreads();

#pragma unroll
        for (int kk = 0; kk < 8; kk++) {
            float a[8], b[8];
            *reinterpret_cast<float4*>(a)     = *reinterpret_cast<float4*>(&As[kk][ty * 8]);
            *reinterpret_cast<float4*>(a + 4) = *reinterpret_cast<float4*>(&As[kk][ty * 8 + 4]);
            *reinterpret_cast<float4*>(b)     = *reinterpret_cast<float4*>(&Bs[kk][tx * 8]);
            *reinterpret_cast<float4*>(b + 4) = *reinterpret_cast<float4*>(&Bs[kk][tx * 8 + 4]);
#pragma unroll
            for (int i = 0; i < 8; i++)
#pragma unroll
                for (int j = 0; j < 8; j++)
                    acc[i][j] = fmaf(a[i], b[j], acc[i][j]);
        }
        __syncthreads();
    }

    // ---- epilogue
    float bv[8];
#pragma unroll
    for (int j = 0; j < 8; j++)
        bv[j] = bias ? bias[col0 + tx * 8 + j] : 0.f;

#pragma unroll
    for (int i = 0; i < 8; i++) {
        float* crow = &C[(size_t)(row0 + ty * 8 + i) * ldc + col0 + tx * 8];
        float4 v0, v1;
        v0.x = acc[i][0] * scale + bv[0];
        v0.y = acc[i][1] * scale + bv[1];
        v0.z = acc[i][2] * scale + bv[2];
        v0.w = acc[i][3] * scale + bv[3];
        v1.x = acc[i][4] * scale + bv[4];
        v1.y = acc[i][5] * scale + bv[5];
        v1.z = acc[i][6] * scale + bv[6];
        v1.w = acc[i][7] * scale + bv[7];
        *reinterpret_cast<float4*>(crow)     = v0;
        *reinterpret_cast<float4*>(crow + 4) = v1;
    }
}

// ---------------- fused RMSNorm (per head, D=128) + RoPE ----------------
// buf layout [S_TOT, HEADS, HDIM]. One warp per (s,h) row, 4 elems per lane.
__global__ void __launch_bounds__(128)
rmsnorm_rope_k(float* __restrict__ buf,
               const float* __restrict__ w_enc, const float* __restrict__ w_img,
               const float* __restrict__ rcos,  const float* __restrict__ rsin)
{
    const int warp = blockIdx.x * 4 + (threadIdx.x >> 5);
    const int lane = threadIdx.x & 31;
    const int s = warp / HEADS;
    const int h = warp % HEADS;

    const float* w = (s < S_TXT) ? w_enc : w_img;
    float* row = buf + (size_t)s * DIM + h * HDIM;

    float4 x = *reinterpret_cast<float4*>(row + lane * 4);
    float ss = x.x * x.x + x.y * x.y + x.z * x.z + x.w * x.w;
#pragma unroll
    for (int o = 16; o; o >>= 1) ss += __shfl_xor_sync(0xffffffffu, ss, o);
    float inv = rsqrtf(ss * (1.f / HDIM) + EPS);

    float4 wv = *reinterpret_cast<const float4*>(w + lane * 4);
    float y0 = x.x * inv * wv.x;
    float y1 = x.y * inv * wv.y;
    float y2 = x.z * inv * wv.z;
    float y3 = x.w * inv * wv.w;

    const float4 c  = *reinterpret_cast<const float4*>(rcos + (size_t)s * HDIM + lane * 4);
    const float4 sn = *reinterpret_cast<const float4*>(rsin + (size_t)s * HDIM + lane * 4);
    // pairs (2i, 2i+1): out[2i] = x[2i]*c - x[2i+1]*s ; out[2i+1] = x[2i+1]*c + x[2i]*s
    float4 o;
    o.x = y0 * c.x - y1 * sn.x;
    o.y = y1 * c.y + y0 * sn.y;
    o.z = y2 * c.z - y3 * sn.z;
    o.w = y3 * c.w + y2 * sn.w;
    *reinterpret_cast<float4*>(row + lane * 4) = o;
}

// ---------------- softmax over rows of length S_TOT ----------------
__global__ void __launch_bounds__(256)
softmax_k(float* __restrict__ s)
{
    float* row = s + (size_t)blockIdx.x * S_TOT;
    const int tid = threadIdx.x;
    __shared__ float red[8];

    float m = -1e30f;
    for (int i = tid; i < S_TOT; i += 256) m = fmaxf(m, row[i]);
#pragma unroll
    for (int o = 16; o; o >>= 1) m = fmaxf(m, __shfl_xor_sync(0xffffffffu, m, o));
    if ((tid & 31) == 0) red[tid >> 5] = m;
    __syncthreads();
    m = red[0];
#pragma unroll
    for (int i = 1; i < 8; i++) m = fmaxf(m, red[i]);
    __syncthreads();

    float sum = 0.f;
    for (int i = tid; i < S_TOT; i += 256) {
        float e = __expf(row[i] - m);
        row[i] = e;
        sum += e;
    }
#pragma unroll
    for (int o = 16; o; o >>= 1) sum += __shfl_xor_sync(0xffffffffu, sum, o);
    if ((tid & 31) == 0) red[tid >> 5] = sum;
    __syncthreads();
    sum = 0.f;
#pragma unroll
    for (int i = 0; i < 8; i++) sum += red[i];
    float inv = 1.f / sum;
    for (int i = tid; i < S_TOT; i += 256) row[i] *= inv;
}

// ---------------- launch ----------------
extern "C" void kernel_launch(void* const* d_in, const int* in_sizes, int n_in,
                              void* d_out, int out_size)
{
    (void)in_sizes; (void)n_in; (void)out_size;
    const float* x    = (const float*)d_in[0];
    const float* ehs  = (const float*)d_in[1];
    const float* rcos = (const float*)d_in[2];
    const float* rsin = (const float*)d_in[3];
    const float* wq   = (const float*)d_in[4];
    const float* wk   = (const float*)d_in[5];
    const float* wv   = (const float*)d_in[6];
    const float* waq  = (const float*)d_in[7];
    const float* wak  = (const float*)d_in[8];
    const float* wav  = (const float*)d_in[9];
    const float* baq  = (const float*)d_in[10];
    const float* bak  = (const float*)d_in[11];
    const float* bav  = (const float*)d_in[12];
    const float* nqw  = (const float*)d_in[13];
    const float* nkw  = (const float*)d_in[14];
    const float* naqw = (const float*)d_in[15];
    const float* nakw = (const float*)d_in[16];
    const float* wo   = (const float*)d_in[17];
    const float* bo   = (const float*)d_in[18];
    const float* wao  = (const float*)d_in[19];
    const float* bao  = (const float*)d_in[20];
    float* out = (float*)d_out;

    float *q, *k, *v, *o, *sc;
    cudaGetSymbolAddress((void**)&q,  g_q);
    cudaGetSymbolAddress((void**)&k,  g_k);
    cudaGetSymbolAddress((void**)&v,  g_v);
    cudaGetSymbolAddress((void**)&o,  g_o);
    cudaGetSymbolAddress((void**)&sc, g_s);

    const dim3 blk(256);
    const long long HS = (long long)S_TOT * S_TOT;

    // ---- QKV projections: enc rows [0,512), img rows [512,2560)
    {
        dim3 gi(DIM / 128, S_IMG / 128, 1);
        gemm_k<true><<<gi, blk>>>(x, wq, nullptr, q + (size_t)S_TXT * DIM,
                                  S_IMG, DIM, DIM, DIM, DIM, DIM, 0, 0, 0, 1.f);
        gemm_k<true><<<gi, blk>>>(x, wk, nullptr, k + (size_t)S_TXT * DIM,
                                  S_IMG, DIM, DIM, DIM, DIM, DIM, 0, 0, 0, 1.f);
        gemm_k<true><<<gi, blk>>>(x, wv, nullptr, v + (size_t)S_TXT * DIM,
                                  S_IMG, DIM, DIM, DIM, DIM, DIM, 0, 0, 0, 1.f);
        dim3 ge(DIM / 128, S_TXT / 128, 1);
        gemm_k<true><<<ge, blk>>>(ehs, waq, baq, q,
                                  S_TXT, DIM, DIM, DIM, DIM, DIM, 0, 0, 0, 1.f);
        gemm_k<true><<<ge, blk>>>(ehs, wak, bak, k,
                                  S_TXT, DIM, DIM, DIM, DIM, DIM, 0, 0, 0, 1.f);
        gemm_k<true><<<ge, blk>>>(ehs, wav, bav, v,
                                  S_TXT, DIM, DIM, DIM, DIM, DIM, 0, 0, 0, 1.f);
    }

    // ---- RMSNorm + RoPE on q, k
    {
        dim3 g((S_TOT * HEADS) / 4);
        rmsnorm_rope_k<<<g, dim3(128)>>>(q, naqw, nqw, rcos, rsin);
        rmsnorm_rope_k<<<g, dim3(128)>>>(k, nakw, nkw, rcos, rsin);
    }

    // ---- scores = scale * Q Kᵀ  (batched over heads)
    {
        dim3 g(S_TOT / 128, S_TOT / 128, HEADS);
        gemm_k<true><<<g, blk>>>(q, k, nullptr, sc,
                                 S_TOT, S_TOT, HDIM, DIM, DIM, S_TOT,
                                 HDIM, HDIM, HS, QK_SCALE);
    }

    // ---- softmax over k
    softmax_k<<<dim3(HEADS * S_TOT), blk>>>(sc);

    // ---- O = P V  (batched over heads)
    {
        dim3 g(HDIM / 128, S_TOT / 128, HEADS);
        gemm_k<false><<<g, blk>>>(sc, v, nullptr, o,
                                  S_TOT, HDIM, S_TOT, S_TOT, DIM, DIM,
                                  HS, HDIM, HDIM, 1.f);
    }

    // ---- output projections: img part first in d_out, then enc part
    {
        dim3 gi(DIM / 128, S_IMG / 128, 1);
        gemm_k<true><<<gi, blk>>>(o + (size_t)S_TXT * DIM, wo, bo, out,
                                  S_IMG, DIM, DIM, DIM, DIM, DIM, 0, 0, 0, 1.f);
        dim3 ge(DIM / 128, S_TXT / 128, 1);
        gemm_k<true><<<ge, blk>>>(o, wao, bao, out + (size_t)S_IMG * DIM,
                                  S_TXT, DIM, DIM, DIM, DIM, DIM, 0, 0, 0, 1.f);
    }
}

// round 2
// speedup vs baseline: 1.9235x; 1.9235x over previous
#include <cuda_runtime.h>
#include <cuda_bf16.h>
#include <math.h>
#include <stdint.h>

// ---------------- problem constants ----------------
#define HEADS   24
#define HDIM    128
#define DIM     3072          // HEADS * HDIM
#define S_TXT   512
#define S_IMG   2048
#define S_TOT   2560          // S_TXT + S_IMG
#define EPS     1e-5f
#define QK_SCALE 0.08838834764831845f   // 1/sqrt(128)

#define PITCH   104           // bf16 pitch for 96-deep k' tiles (16B-aligned rows)
#define SMEM_BYTES (2 * 128 * PITCH * 2)

// ---------------- scratch (device globals; allocation-free) ----------------
__device__ float g_q[(size_t)S_TOT * DIM];
__device__ float g_k[(size_t)S_TOT * DIM];
__device__ float g_v[(size_t)S_TOT * DIM];
__device__ float g_o[(size_t)S_TOT * DIM];
__device__ float g_s[(size_t)HEADS * S_TOT * S_TOT];   // attention scores/probs

// ---------------- helpers ----------------
struct bf16x4 { __nv_bfloat162 a, b; };

__device__ __forceinline__ void split4(float4 v, bf16x4& hi, bf16x4& lo) {
    __nv_bfloat162 h01 = __floats2bfloat162_rn(v.x, v.y);
    __nv_bfloat162 h23 = __floats2bfloat162_rn(v.z, v.w);
    float2 f01 = __bfloat1622float2(h01);
    float2 f23 = __bfloat1622float2(h23);
    __nv_bfloat162 l01 = __floats2bfloat162_rn(v.x - f01.x, v.y - f01.y);
    __nv_bfloat162 l23 = __floats2bfloat162_rn(v.z - f23.x, v.w - f23.y);
    hi.a = h01; hi.b = h23;
    lo.a = l01; lo.b = l23;
}

__device__ __forceinline__ uint32_t smem_u32(const void* p) {
    return static_cast<uint32_t>(__cvta_generic_to_shared(p));
}

__device__ __forceinline__ void ldm_x4(uint32_t addr, uint32_t& r0, uint32_t& r1,
                                       uint32_t& r2, uint32_t& r3) {
    asm volatile("ldmatrix.sync.aligned.m8n8.x4.shared.b16 {%0,%1,%2,%3}, [%4];"
                 : "=r"(r0), "=r"(r1), "=r"(r2), "=r"(r3) : "r"(addr));
}

__device__ __forceinline__ void mma16816(float& c0, float& c1, float& c2, float& c3,
                                         uint32_t a0, uint32_t a1, uint32_t a2, uint32_t a3,
                                         uint32_t b0, uint32_t b1) {
    asm volatile("mma.sync.aligned.m16n8k16.row.col.f32.bf16.bf16.f32 "
                 "{%0,%1,%2,%3}, {%4,%5,%6,%7}, {%8,%9}, {%0,%1,%2,%3};"
                 : "+f"(c0), "+f"(c1), "+f"(c2), "+f"(c3)
                 : "r"(a0), "r"(a1), "r"(a2), "r"(a3), "r"(b0), "r"(b1));
}

// ---------------- split-bf16 tensor-core GEMM, 128x128 CTA tile ----------------
// NT = true :  C[m,n] = scale * sum_k A[m,k] * B[n,k]   (+ bias[n])
// NT = false:  C[m,n] = scale * sum_k A[m,k] * B[k,n]   (+ bias[n])
// Requires M%128==0, N%128==0, K%32==0, row strides %4==0, 16B-aligned bases.
// Accuracy: fp32-like via split accumulation hiA*hiB + hiA*loB + loA*hiB.
template<bool NT>
__global__ void __launch_bounds__(256)
gemm_bf16_k(const float* __restrict__ A, const float* __restrict__ B,
            const float* __restrict__ bias, float* __restrict__ C,
            int M, int N, int K, int lda, int ldb, int ldc,
            long long sA, long long sB, long long sC, float scale)
{
    extern __shared__ __nv_bfloat16 smem[];
    __nv_bfloat16* As = smem;               // [128][PITCH], sections k'=[hi|hi|lo]
    __nv_bfloat16* Bs = smem + 128 * PITCH; // [128][PITCH], sections k'=[hi|lo|hi]

    A += (size_t)blockIdx.z * sA;
    B += (size_t)blockIdx.z * sB;
    C += (size_t)blockIdx.z * sC;

    const int row0 = blockIdx.y * 128;
    const int col0 = blockIdx.x * 128;
    const int tid  = threadIdx.x;
    const int lane = tid & 31;
    const int warp = tid >> 5;
    const int wm   = warp & 3;      // m block (32 rows)
    const int wn   = warp >> 2;     // n block (64 cols)

    // ---- staging thread maps
    const int at_m = tid >> 1;            // 0..127
    const int at_k = (tid & 1) * 4;       // 0 or 4  (+ l*8)
    // NN B map
    const int bt_k = tid >> 3;            // 0..31
    const int bt_n = (tid & 7) * 4;       // 0..28 (+ l*32)

    // ---- ldmatrix per-lane address bases
    const int m_off_A = (lane & 7) + ((lane >> 3) & 1) * 8;
    const int k_off_A = (lane >> 4) * 8;
    const int n_off_B = (lane & 7) + (lane >> 4) * 8;
    const int k_off_B = ((lane >> 3) & 1) * 8;

    uint32_t aBase[2], bBase[4];
#pragma unroll
    for (int mi = 0; mi < 2; mi++)
        aBase[mi] = smem_u32(&As[(wm * 32 + mi * 16 + m_off_A) * PITCH + k_off_A]);
#pragma unroll
    for (int np = 0; np < 4; np++)
        bBase[np] = smem_u32(&Bs[(wn * 64 + np * 16 + n_off_B) * PITCH + k_off_B]);

    float acc[2][8][4];
#pragma unroll
    for (int i = 0; i < 2; i++)
#pragma unroll
        for (int j = 0; j < 8; j++)
#pragma unroll
            for (int c = 0; c < 4; c++) acc[i][j][c] = 0.f;

    const int nc = K / 32;
    float4 aR[4], bR[4];

    // prefetch chunk 0
#pragma unroll
    for (int l = 0; l < 4; l++)
        aR[l] = *reinterpret_cast<const float4*>(&A[(size_t)(row0 + at_m) * lda + at_k + l * 8]);
    if (NT) {
#pragma unroll
        for (int l = 0; l < 4; l++)
            bR[l] = *reinterpret_cast<const float4*>(&B[(size_t)(col0 + at_m) * ldb + at_k + l * 8]);
    } else {
#pragma unroll
        for (int l = 0; l < 4; l++)
            bR[l] = *reinterpret_cast<const float4*>(&B[(size_t)bt_k * ldb + col0 + bt_n + l * 32]);
    }

    for (int c = 0; c < nc; c++) {
        // ---- convert & store staged registers to smem
#pragma unroll
        for (int l = 0; l < 4; l++) {
            bf16x4 hi, lo;
            split4(aR[l], hi, lo);
            const int kb = at_k + l * 8;
            *reinterpret_cast<bf16x4*>(&As[at_m * PITCH + kb])      = hi;
            *reinterpret_cast<bf16x4*>(&As[at_m * PITCH + 32 + kb]) = hi;
            *reinterpret_cast<bf16x4*>(&As[at_m * PITCH + 64 + kb]) = lo;
        }
        if (NT) {
#pragma unroll
            for (int l = 0; l < 4; l++) {
                bf16x4 hi, lo;
                split4(bR[l], hi, lo);
                const int kb = at_k + l * 8;
                *reinterpret_cast<bf16x4*>(&Bs[at_m * PITCH + kb])      = hi;
                *reinterpret_cast<bf16x4*>(&Bs[at_m * PITCH + 32 + kb]) = lo;
                *reinterpret_cast<bf16x4*>(&Bs[at_m * PITCH + 64 + kb]) = hi;
            }
        } else {
#pragma unroll
            for (int l = 0; l < 4; l++) {
                bf16x4 hi, lo;
                split4(bR[l], hi, lo);
                const __nv_bfloat16 h[4] = {hi.a.x, hi.a.y, hi.b.x, hi.b.y};
                const __nv_bfloat16 lw[4] = {lo.a.x, lo.a.y, lo.b.x, lo.b.y};
#pragma unroll
                for (int e = 0; e < 4; e++) {
                    const int n = bt_n + l * 32 + e;
                    Bs[n * PITCH + bt_k]      = h[e];
                    Bs[n * PITCH + 32 + bt_k] = lw[e];
                    Bs[n * PITCH + 64 + bt_k] = h[e];
                }
            }
        }
        __syncthreads();

        // ---- prefetch next chunk
        if (c + 1 < nc) {
            const int k0 = (c + 1) * 32;
#pragma unroll
            for (int l = 0; l < 4; l++)
                aR[l] = *reinterpret_cast<const float4*>(
                    &A[(size_t)(row0 + at_m) * lda + k0 + at_k + l * 8]);
            if (NT) {
#pragma unroll
                for (int l = 0; l < 4; l++)
                    bR[l] = *reinterpret_cast<const float4*>(
                        &B[(size_t)(col0 + at_m) * ldb + k0 + at_k + l * 8]);
            } else {
#pragma unroll
                for (int l = 0; l < 4; l++)
                    bR[l] = *reinterpret_cast<const float4*>(
                        &B[(size_t)(k0 + bt_k) * ldb + col0 + bt_n + l * 32]);
            }
        }

        // ---- 6 k16 steps over the 96-deep split tile
#pragma unroll
        for (int ks = 0; ks < 6; ks++) {
            const int koff = ks * 16 * 2;   // byte offset
            uint32_t Ar[2][4], Br[8][2];
#pragma unroll
            for (int mi = 0; mi < 2; mi++)
                ldm_x4(aBase[mi] + koff, Ar[mi][0], Ar[mi][1], Ar[mi][2], Ar[mi][3]);
#pragma unroll
            for (int np = 0; np < 4; np++)
                ldm_x4(bBase[np] + koff, Br[2 * np][0], Br[2 * np][1],
                       Br[2 * np + 1][0], Br[2 * np + 1][1]);
#pragma unroll
            for (int mi = 0; mi < 2; mi++)
#pragma unroll
                for (int nj = 0; nj < 8; nj++)
                    mma16816(acc[mi][nj][0], acc[mi][nj][1], acc[mi][nj][2], acc[mi][nj][3],
                             Ar[mi][0], Ar[mi][1], Ar[mi][2], Ar[mi][3],
                             Br[nj][0], Br[nj][1]);
        }
        __syncthreads();
    }

    // ---- epilogue
#pragma unroll
    for (int mi = 0; mi < 2; mi++) {
#pragma unroll
        for (int nj = 0; nj < 8; nj++) {
            const int row = row0 + wm * 32 + mi * 16 + (lane >> 2);
            const int col = col0 + wn * 64 + nj * 8 + (lane & 3) * 2;
            float b0 = bias ? bias[col]     : 0.f;
            float b1 = bias ? bias[col + 1] : 0.f;
            float2 v0, v1;
            v0.x = acc[mi][nj][0] * scale + b0;
            v0.y = acc[mi][nj][1] * scale + b1;
            v1.x = acc[mi][nj][2] * scale + b0;
            v1.y = acc[mi][nj][3] * scale + b1;
            *reinterpret_cast<float2*>(&C[(size_t)row * ldc + col])       = v0;
            *reinterpret_cast<float2*>(&C[(size_t)(row + 8) * ldc + col]) = v1;
        }
    }
}

// ---------------- fused RMSNorm (per head, D=128) + RoPE ----------------
__global__ void __launch_bounds__(128)
rmsnorm_rope_k(float* __restrict__ buf,
               const float* __restrict__ w_enc, const float* __restrict__ w_img,
               const float* __restrict__ rcos,  const float* __restrict__ rsin)
{
    const int warp = blockIdx.x * 4 + (threadIdx.x >> 5);
    const int lane = threadIdx.x & 31;
    const int s = warp / HEADS;
    const int h = warp % HEADS;

    const float* w = (s < S_TXT) ? w_enc : w_img;
    float* row = buf + (size_t)s * DIM + h * HDIM;

    float4 x = *reinterpret_cast<float4*>(row + lane * 4);
    float ss = x.x * x.x + x.y * x.y + x.z * x.z + x.w * x.w;
#pragma unroll
    for (int o = 16; o; o >>= 1) ss += __shfl_xor_sync(0xffffffffu, ss, o);
    float inv = rsqrtf(ss * (1.f / HDIM) + EPS);

    float4 wv = *reinterpret_cast<const float4*>(w + lane * 4);
    float y0 = x.x * inv * wv.x;
    float y1 = x.y * inv * wv.y;
    float y2 = x.z * inv * wv.z;
    float y3 = x.w * inv * wv.w;

    const float4 c  = *reinterpret_cast<const float4*>(rcos + (size_t)s * HDIM + lane * 4);
    const float4 sn = *reinterpret_cast<const float4*>(rsin + (size_t)s * HDIM + lane * 4);
    float4 o;
    o.x = y0 * c.x - y1 * sn.x;
    o.y = y1 * c.y + y0 * sn.y;
    o.z = y2 * c.z - y3 * sn.z;
    o.w = y3 * c.w + y2 * sn.w;
    *reinterpret_cast<float4*>(row + lane * 4) = o;
}

// ---------------- softmax over rows of length S_TOT ----------------
__global__ void __launch_bounds__(256)
softmax_k(float* __restrict__ s)
{
    float* row = s + (size_t)blockIdx.x * S_TOT;
    const int tid = threadIdx.x;
    __shared__ float red[8];

    float m = -1e30f;
    for (int i = tid; i < S_TOT; i += 256) m = fmaxf(m, row[i]);
#pragma unroll
    for (int o = 16; o; o >>= 1) m = fmaxf(m, __shfl_xor_sync(0xffffffffu, m, o));
    if ((tid & 31) == 0) red[tid >> 5] = m;
    __syncthreads();
    m = red[0];
#pragma unroll
    for (int i = 1; i < 8; i++) m = fmaxf(m, red[i]);
    __syncthreads();

    float sum = 0.f;
    for (int i = tid; i < S_TOT; i += 256) {
        float e = __expf(row[i] - m);
        row[i] = e;
        sum += e;
    }
#pragma unroll
    for (int o = 16; o; o >>= 1) sum += __shfl_xor_sync(0xffffffffu, sum, o);
    if ((tid & 31) == 0) red[tid >> 5] = sum;
    __syncthreads();
    sum = 0.f;
#pragma unroll
    for (int i = 0; i < 8; i++) sum += red[i];
    float inv = 1.f / sum;
    for (int i = tid; i < S_TOT; i += 256) row[i] *= inv;
}

// ---------------- launch ----------------
extern "C" void kernel_launch(void* const* d_in, const int* in_sizes, int n_in,
                              void* d_out, int out_size)
{
    (void)in_sizes; (void)n_in; (void)out_size;
    const float* x    = (const float*)d_in[0];
    const float* ehs  = (const float*)d_in[1];
    const float* rcos = (const float*)d_in[2];
    const float* rsin = (const float*)d_in[3];
    const float* wq   = (const float*)d_in[4];
    const float* wk   = (const float*)d_in[5];
    const float* wv   = (const float*)d_in[6];
    const float* waq  = (const float*)d_in[7];
    const float* wak  = (const float*)d_in[8];
    const float* wav  = (const float*)d_in[9];
    const float* baq  = (const float*)d_in[10];
    const float* bak  = (const float*)d_in[11];
    const float* bav  = (const float*)d_in[12];
    const float* nqw  = (const float*)d_in[13];
    const float* nkw  = (const float*)d_in[14];
    const float* naqw = (const float*)d_in[15];
    const float* nakw = (const float*)d_in[16];
    const float* wo   = (const float*)d_in[17];
    const float* bo   = (const float*)d_in[18];
    const float* wao  = (const float*)d_in[19];
    const float* bao  = (const float*)d_in[20];
    float* out = (float*)d_out;

    float *q, *k, *v, *o, *sc;
    cudaGetSymbolAddress((void**)&q,  g_q);
    cudaGetSymbolAddress((void**)&k,  g_k);
    cudaGetSymbolAddress((void**)&v,  g_v);
    cudaGetSymbolAddress((void**)&o,  g_o);
    cudaGetSymbolAddress((void**)&sc, g_s);

    cudaFuncSetAttribute(gemm_bf16_k<true>,  cudaFuncAttributeMaxDynamicSharedMemorySize, SMEM_BYTES);
    cudaFuncSetAttribute(gemm_bf16_k<false>, cudaFuncAttributeMaxDynamicSharedMemorySize, SMEM_BYTES);

    const dim3 blk(256);
    const long long HS = (long long)S_TOT * S_TOT;

    // ---- QKV projections: enc rows [0,512), img rows [512,2560)
    {
        dim3 gi(DIM / 128, S_IMG / 128, 1);
        gemm_bf16_k<true><<<gi, blk, SMEM_BYTES>>>(x, wq, nullptr, q + (size_t)S_TXT * DIM,
                                  S_IMG, DIM, DIM, DIM, DIM, DIM, 0, 0, 0, 1.f);
        gemm_bf16_k<true><<<gi, blk, SMEM_BYTES>>>(x, wk, nullptr, k + (size_t)S_TXT * DIM,
                                  S_IMG, DIM, DIM, DIM, DIM, DIM, 0, 0, 0, 1.f);
        gemm_bf16_k<true><<<gi, blk, SMEM_BYTES>>>(x, wv, nullptr, v + (size_t)S_TXT * DIM,
                                  S_IMG, DIM, DIM, DIM, DIM, DIM, 0, 0, 0, 1.f);
        dim3 ge(DIM / 128, S_TXT / 128, 1);
        gemm_bf16_k<true><<<ge, blk, SMEM_BYTES>>>(ehs, waq, baq, q,
                                  S_TXT, DIM, DIM, DIM, DIM, DIM, 0, 0, 0, 1.f);
        gemm_bf16_k<true><<<ge, blk, SMEM_BYTES>>>(ehs, wak, bak, k,
                                  S_TXT, DIM, DIM, DIM, DIM, DIM, 0, 0, 0, 1.f);
        gemm_bf16_k<true><<<ge, blk, SMEM_BYTES>>>(ehs, wav, bav, v,
                                  S_TXT, DIM, DIM, DIM, DIM, DIM, 0, 0, 0, 1.f);
    }

    // ---- RMSNorm + RoPE on q, k
    {
        dim3 g((S_TOT * HEADS) / 4);
        rmsnorm_rope_k<<<g, dim3(128)>>>(q, naqw, nqw, rcos, rsin);
        rmsnorm_rope_k<<<g, dim3(128)>>>(k, nakw, nkw, rcos, rsin);
    }

    // ---- scores = scale * Q Kᵀ  (batched over heads)
    {
        dim3 g(S_TOT / 128, S_TOT / 128, HEADS);
        gemm_bf16_k<true><<<g, blk, SMEM_BYTES>>>(q, k, nullptr, sc,
                                 S_TOT, S_TOT, HDIM, DIM, DIM, S_TOT,
                                 HDIM, HDIM, HS, QK_SCALE);
    }

    // ---- softmax over k
    softmax_k<<<dim3(HEADS * S_TOT), blk>>>(sc);

    // ---- O = P V  (batched over heads)
    {
        dim3 g(HDIM / 128, S_TOT / 128, HEADS);
        gemm_bf16_k<false><<<g, blk, SMEM_BYTES>>>(sc, v, nullptr, o,
                                  S_TOT, HDIM, S_TOT, S_TOT, DIM, DIM,
                                  HS, HDIM, HDIM, 1.f);
    }

    // ---- output projections: img part first in d_out, then enc part
    {
        dim3 gi(DIM / 128, S_IMG / 128, 1);
        gemm_bf16_k<true><<<gi, blk, SMEM_BYTES>>>(o + (size_t)S_TXT * DIM, wo, bo, out,
                                  S_IMG, DIM, DIM, DIM, DIM, DIM, 0, 0, 0, 1.f);
        dim3 ge(DIM / 128, S_TXT / 128, 1);
        gemm_bf16_k<true><<<ge, blk, SMEM_BYTES>>>(o, wao, bao, out + (size_t)S_IMG * DIM,
                                  S_TXT, DIM, DIM, DIM, DIM, DIM, 0, 0, 0, 1.f);
    }
}

// round 3
// speedup vs baseline: 2.3665x; 1.2303x over previous
#include <cuda_runtime.h>
#include <cuda_bf16.h>
#include <math.h>
#include <stdint.h>

// ---------------- problem constants ----------------
#define HEADS   24
#define HDIM    128
#define DIM     3072          // HEADS * HDIM
#define S_TXT   512
#define S_IMG   2048
#define S_TOT   2560          // S_TXT + S_IMG
#define EPS     1e-5f
#define QK_SCALE 0.08838834764831845f   // 1/sqrt(128)

#define PITCH      104                  // bf16 pitch for 96-deep k' tiles
#define MAT_ELEMS  (128 * PITCH)        // elems per A or B tile
#define BUF_ELEMS  (2 * MAT_ELEMS)      // A+B per buffer
#define BUF_BYTES  (BUF_ELEMS * 2)      // 53248
#define SMEM_BYTES (2 * BUF_BYTES)      // 106496 (double buffered)

// ---------------- scratch (device globals; allocation-free) ----------------
__device__ float g_q[(size_t)S_TOT * DIM];
__device__ float g_k[(size_t)S_TOT * DIM];
__device__ float g_v[(size_t)S_TOT * DIM];
__device__ float g_o[(size_t)S_TOT * DIM];
__device__ float g_s[(size_t)HEADS * S_TOT * S_TOT];   // attention scores/probs

// ---------------- helpers ----------------
struct bf16x4 { __nv_bfloat162 a, b; };

__device__ __forceinline__ void split4(float4 v, bf16x4& hi, bf16x4& lo) {
    __nv_bfloat162 h01 = __floats2bfloat162_rn(v.x, v.y);
    __nv_bfloat162 h23 = __floats2bfloat162_rn(v.z, v.w);
    float2 f01 = __bfloat1622float2(h01);
    float2 f23 = __bfloat1622float2(h23);
    __nv_bfloat162 l01 = __floats2bfloat162_rn(v.x - f01.x, v.y - f01.y);
    __nv_bfloat162 l23 = __floats2bfloat162_rn(v.z - f23.x, v.w - f23.y);
    hi.a = h01; hi.b = h23;
    lo.a = l01; lo.b = l23;
}

__device__ __forceinline__ uint32_t smem_u32(const void* p) {
    return static_cast<uint32_t>(__cvta_generic_to_shared(p));
}

__device__ __forceinline__ void ldm_x4(uint32_t addr, uint32_t& r0, uint32_t& r1,
                                       uint32_t& r2, uint32_t& r3) {
    asm volatile("ldmatrix.sync.aligned.m8n8.x4.shared.b16 {%0,%1,%2,%3}, [%4];"
                 : "=r"(r0), "=r"(r1), "=r"(r2), "=r"(r3) : "r"(addr));
}

__device__ __forceinline__ void mma16816(float& c0, float& c1, float& c2, float& c3,
                                         uint32_t a0, uint32_t a1, uint32_t a2, uint32_t a3,
                                         uint32_t b0, uint32_t b1) {
    asm volatile("mma.sync.aligned.m16n8k16.row.col.f32.bf16.bf16.f32 "
                 "{%0,%1,%2,%3}, {%4,%5,%6,%7}, {%8,%9}, {%0,%1,%2,%3};"
                 : "+f"(c0), "+f"(c1), "+f"(c2), "+f"(c3)
                 : "r"(a0), "r"(a1), "r"(a2), "r"(a3), "r"(b0), "r"(b1));
}

// ---------------- split-bf16 tensor-core GEMM body, 128x128 CTA tile ----------------
// NT = true :  C[m,n] = scale * sum_k A[m,k] * B[n,k]   (+ bias[n])
// NT = false:  C[m,n] = scale * sum_k A[m,k] * B[k,n]   (+ bias[n])
// Requires M%128==0, N%128==0, K%32==0, row strides %4==0, 16B-aligned bases.
// Accuracy: fp32-like via split accumulation hiA*hiB + hiA*loB + loA*hiB.
// Double-buffered smem pipeline, one __syncthreads per K-chunk.
template<bool NT>
__device__ __forceinline__ void gemm_body(
    const float* __restrict__ A, const float* __restrict__ B,
    const float* __restrict__ bias, float* __restrict__ C,
    int K, int lda, int ldb, int ldc, float scale)
{
    extern __shared__ __nv_bfloat16 smem[];

    const int row0 = blockIdx.y * 128;
    const int col0 = blockIdx.x * 128;
    const int tid  = threadIdx.x;
    const int lane = tid & 31;
    const int warp = tid >> 5;
    const int wm   = warp & 3;      // m block (32 rows)
    const int wn   = warp >> 2;     // n block (64 cols)

    // ---- staging thread maps
    const int at_m = tid >> 1;            // 0..127
    const int at_k = (tid & 1) * 4;       // 0 or 4  (+ l*8)
    const int bt_k = tid >> 3;            // 0..31      (NN map)
    const int bt_n = (tid & 7) * 4;       // 0..28 (+ l*32)

    // ---- ldmatrix per-lane address bases (buffer 0)
    const int m_off_A = (lane & 7) + ((lane >> 3) & 1) * 8;
    const int k_off_A = (lane >> 4) * 8;
    const int n_off_B = (lane & 7) + (lane >> 4) * 8;
    const int k_off_B = ((lane >> 3) & 1) * 8;

    uint32_t aBase[2], bBase[4];
#pragma unroll
    for (int mi = 0; mi < 2; mi++)
        aBase[mi] = smem_u32(&smem[(wm * 32 + mi * 16 + m_off_A) * PITCH + k_off_A]);
#pragma unroll
    for (int np = 0; np < 4; np++)
        bBase[np] = smem_u32(&smem[MAT_ELEMS + (wn * 64 + np * 16 + n_off_B) * PITCH + k_off_B]);

    float acc[2][8][4];
#pragma unroll
    for (int i = 0; i < 2; i++)
#pragma unroll
        for (int j = 0; j < 8; j++)
#pragma unroll
            for (int c = 0; c < 4; c++) acc[i][j][c] = 0.f;

    const int nc = K / 32;
    float4 aR[4], bR[4];

    auto ldg_chunk = [&](int k0) {
#pragma unroll
        for (int l = 0; l < 4; l++)
            aR[l] = *reinterpret_cast<const float4*>(
                &A[(size_t)(row0 + at_m) * lda + k0 + at_k + l * 8]);
        if (NT) {
#pragma unroll
            for (int l = 0; l < 4; l++)
                bR[l] = *reinterpret_cast<const float4*>(
                    &B[(size_t)(col0 + at_m) * ldb + k0 + at_k + l * 8]);
        } else {
#pragma unroll
            for (int l = 0; l < 4; l++)
                bR[l] = *reinterpret_cast<const float4*>(
                    &B[(size_t)(k0 + bt_k) * ldb + col0 + bt_n + l * 32]);
        }
    };

    auto stage_chunk = [&](int buf) {
        __nv_bfloat16* As = smem + buf * BUF_ELEMS;
        __nv_bfloat16* Bs = As + MAT_ELEMS;
#pragma unroll
        for (int l = 0; l < 4; l++) {
            bf16x4 hi, lo;
            split4(aR[l], hi, lo);
            const int kb = at_k + l * 8;
            *reinterpret_cast<bf16x4*>(&As[at_m * PITCH + kb])      = hi;
            *reinterpret_cast<bf16x4*>(&As[at_m * PITCH + 32 + kb]) = hi;
            *reinterpret_cast<bf16x4*>(&As[at_m * PITCH + 64 + kb]) = lo;
        }
        if (NT) {
#pragma unroll
            for (int l = 0; l < 4; l++) {
                bf16x4 hi, lo;
                split4(bR[l], hi, lo);
                const int kb = at_k + l * 8;
                *reinterpret_cast<bf16x4*>(&Bs[at_m * PITCH + kb])      = hi;
                *reinterpret_cast<bf16x4*>(&Bs[at_m * PITCH + 32 + kb]) = lo;
                *reinterpret_cast<bf16x4*>(&Bs[at_m * PITCH + 64 + kb]) = hi;
            }
        } else {
#pragma unroll
            for (int l = 0; l < 4; l++) {
                bf16x4 hi, lo;
                split4(bR[l], hi, lo);
                const __nv_bfloat16 h[4]  = {hi.a.x, hi.a.y, hi.b.x, hi.b.y};
                const __nv_bfloat16 lw[4] = {lo.a.x, lo.a.y, lo.b.x, lo.b.y};
#pragma unroll
                for (int e = 0; e < 4; e++) {
                    const int n = bt_n + l * 32 + e;
                    Bs[n * PITCH + bt_k]      = h[e];
                    Bs[n * PITCH + 32 + bt_k] = lw[e];
                    Bs[n * PITCH + 64 + bt_k] = h[e];
                }
            }
        }
    };

    // ---- prologue: fill buffer 0
    ldg_chunk(0);
    stage_chunk(0);
    __syncthreads();

    for (int c = 0; c < nc; c++) {
        const int cur = c & 1;
        const bool more = (c + 1 < nc);
        if (more) ldg_chunk((c + 1) * 32);      // overlaps with MMA phase below

        const uint32_t bufOff = (uint32_t)cur * BUF_BYTES;

        // ---- 6 k16 steps over the 96-deep split tile
#pragma unroll
        for (int ks = 0; ks < 6; ks++) {
            const uint32_t koff = bufOff + ks * 16 * 2;
            uint32_t Ar[2][4], Br[8][2];
#pragma unroll
            for (int mi = 0; mi < 2; mi++)
                ldm_x4(aBase[mi] + koff, Ar[mi][0], Ar[mi][1], Ar[mi][2], Ar[mi][3]);
#pragma unroll
            for (int np = 0; np < 4; np++)
                ldm_x4(bBase[np] + koff, Br[2 * np][0], Br[2 * np][1],
                       Br[2 * np + 1][0], Br[2 * np + 1][1]);
#pragma unroll
            for (int mi = 0; mi < 2; mi++)
#pragma unroll
                for (int nj = 0; nj < 8; nj++)
                    mma16816(acc[mi][nj][0], acc[mi][nj][1], acc[mi][nj][2], acc[mi][nj][3],
                             Ar[mi][0], Ar[mi][1], Ar[mi][2], Ar[mi][3],
                             Br[nj][0], Br[nj][1]);
        }

        if (more) stage_chunk(cur ^ 1);          // write other buffer (safe: sync of prev iter)
        __syncthreads();
    }

    // ---- epilogue
#pragma unroll
    for (int mi = 0; mi < 2; mi++) {
#pragma unroll
        for (int nj = 0; nj < 8; nj++) {
            const int row = row0 + wm * 32 + mi * 16 + (lane >> 2);
            const int col = col0 + wn * 64 + nj * 8 + (lane & 3) * 2;
            float b0 = bias ? bias[col]     : 0.f;
            float b1 = bias ? bias[col + 1] : 0.f;
            float2 v0, v1;
            v0.x = acc[mi][nj][0] * scale + b0;
            v0.y = acc[mi][nj][1] * scale + b1;
            v1.x = acc[mi][nj][2] * scale + b0;
            v1.y = acc[mi][nj][3] * scale + b1;
            *reinterpret_cast<float2*>(&C[(size_t)row * ldc + col])       = v0;
            *reinterpret_cast<float2*>(&C[(size_t)(row + 8) * ldc + col]) = v1;
        }
    }
}

// ---------------- kernels ----------------
template<bool NT>
__global__ void __launch_bounds__(256)
gemm_bf16_k(const float* __restrict__ A, const float* __restrict__ B,
            const float* __restrict__ bias, float* __restrict__ C,
            int K, int lda, int ldb, int ldc,
            long long sA, long long sB, long long sC, float scale)
{
    A += (size_t)blockIdx.z * sA;
    B += (size_t)blockIdx.z * sB;
    C += (size_t)blockIdx.z * sC;
    gemm_body<NT>(A, B, bias, C, K, lda, ldb, ldc, scale);
}

// batched over 3 weight matrices (Q/K/V) via blockIdx.z
struct Ptr3 {
    const float *B0, *B1, *B2;
    float *C0, *C1, *C2;
    const float *b0, *b1, *b2;
};

__global__ void __launch_bounds__(256)
qkv_k(const float* __restrict__ A, Ptr3 p, int K, int lda, int ldb, int ldc, float scale)
{
    const float* B; float* C; const float* bias;
    if (blockIdx.z == 0)      { B = p.B0; C = p.C0; bias = p.b0; }
    else if (blockIdx.z == 1) { B = p.B1; C = p.C1; bias = p.b1; }
    else                      { B = p.B2; C = p.C2; bias = p.b2; }
    gemm_body<true>(A, B, bias, C, K, lda, ldb, ldc, scale);
}

// ---------------- fused RMSNorm (per head, D=128) + RoPE ----------------
__global__ void __launch_bounds__(128)
rmsnorm_rope_k(float* __restrict__ buf,
               const float* __restrict__ w_enc, const float* __restrict__ w_img,
               const float* __restrict__ rcos,  const float* __restrict__ rsin)
{
    const int warp = blockIdx.x * 4 + (threadIdx.x >> 5);
    const int lane = threadIdx.x & 31;
    const int s = warp / HEADS;
    const int h = warp % HEADS;

    const float* w = (s < S_TXT) ? w_enc : w_img;
    float* row = buf + (size_t)s * DIM + h * HDIM;

    float4 x = *reinterpret_cast<float4*>(row + lane * 4);
    float ss = x.x * x.x + x.y * x.y + x.z * x.z + x.w * x.w;
#pragma unroll
    for (int o = 16; o; o >>= 1) ss += __shfl_xor_sync(0xffffffffu, ss, o);
    float inv = rsqrtf(ss * (1.f / HDIM) + EPS);

    float4 wv = *reinterpret_cast<const float4*>(w + lane * 4);
    float y0 = x.x * inv * wv.x;
    float y1 = x.y * inv * wv.y;
    float y2 = x.z * inv * wv.z;
    float y3 = x.w * inv * wv.w;

    const float4 c  = *reinterpret_cast<const float4*>(rcos + (size_t)s * HDIM + lane * 4);
    const float4 sn = *reinterpret_cast<const float4*>(rsin + (size_t)s * HDIM + lane * 4);
    float4 o;
    o.x = y0 * c.x - y1 * sn.x;
    o.y = y1 * c.y + y0 * sn.y;
    o.z = y2 * c.z - y3 * sn.z;
    o.w = y3 * c.w + y2 * sn.w;
    *reinterpret_cast<float4*>(row + lane * 4) = o;
}

// ---------------- softmax over rows of length S_TOT ----------------
__global__ void __launch_bounds__(256)
softmax_k(float* __restrict__ s)
{
    float* row = s + (size_t)blockIdx.x * S_TOT;
    const int tid = threadIdx.x;
    __shared__ float red[8];

    float m = -1e30f;
    for (int i = tid; i < S_TOT; i += 256) m = fmaxf(m, row[i]);
#pragma unroll
    for (int o = 16; o; o >>= 1) m = fmaxf(m, __shfl_xor_sync(0xffffffffu, m, o));
    if ((tid & 31) == 0) red[tid >> 5] = m;
    __syncthreads();
    m = red[0];
#pragma unroll
    for (int i = 1; i < 8; i++) m = fmaxf(m, red[i]);
    __syncthreads();

    float sum = 0.f;
    for (int i = tid; i < S_TOT; i += 256) {
        float e = __expf(row[i] - m);
        row[i] = e;
        sum += e;
    }
#pragma unroll
    for (int o = 16; o; o >>= 1) sum += __shfl_xor_sync(0xffffffffu, sum, o);
    if ((tid & 31) == 0) red[tid >> 5] = sum;
    __syncthreads();
    sum = 0.f;
#pragma unroll
    for (int i = 0; i < 8; i++) sum += red[i];
    float inv = 1.f / sum;
    for (int i = tid; i < S_TOT; i += 256) row[i] *= inv;
}

// ---------------- launch ----------------
extern "C" void kernel_launch(void* const* d_in, const int* in_sizes, int n_in,
                              void* d_out, int out_size)
{
    (void)in_sizes; (void)n_in; (void)out_size;
    const float* x    = (const float*)d_in[0];
    const float* ehs  = (const float*)d_in[1];
    const float* rcos = (const float*)d_in[2];
    const float* rsin = (const float*)d_in[3];
    const float* wq   = (const float*)d_in[4];
    const float* wk   = (const float*)d_in[5];
    const float* wv   = (const float*)d_in[6];
    const float* waq  = (const float*)d_in[7];
    const float* wak  = (const float*)d_in[8];
    const float* wav  = (const float*)d_in[9];
    const float* baq  = (const float*)d_in[10];
    const float* bak  = (const float*)d_in[11];
    const float* bav  = (const float*)d_in[12];
    const float* nqw  = (const float*)d_in[13];
    const float* nkw  = (const float*)d_in[14];
    const float* naqw = (const float*)d_in[15];
    const float* nakw = (const float*)d_in[16];
    const float* wo   = (const float*)d_in[17];
    const float* bo   = (const float*)d_in[18];
    const float* wao  = (const float*)d_in[19];
    const float* bao  = (const float*)d_in[20];
    float* out = (float*)d_out;

    float *q, *k, *v, *o, *sc;
    cudaGetSymbolAddress((void**)&q,  g_q);
    cudaGetSymbolAddress((void**)&k,  g_k);
    cudaGetSymbolAddress((void**)&v,  g_v);
    cudaGetSymbolAddress((void**)&o,  g_o);
    cudaGetSymbolAddress((void**)&sc, g_s);

    cudaFuncSetAttribute(gemm_bf16_k<true>,  cudaFuncAttributeMaxDynamicSharedMemorySize, SMEM_BYTES);
    cudaFuncSetAttribute(gemm_bf16_k<false>, cudaFuncAttributeMaxDynamicSharedMemorySize, SMEM_BYTES);
    cudaFuncSetAttribute(qkv_k,              cudaFuncAttributeMaxDynamicSharedMemorySize, SMEM_BYTES);

    const dim3 blk(256);
    const long long HS = (long long)S_TOT * S_TOT;

    // ---- QKV projections (batched over {q,k,v} weights via z)
    {
        Ptr3 pi = { wq, wk, wv,
                    q + (size_t)S_TXT * DIM, k + (size_t)S_TXT * DIM, v + (size_t)S_TXT * DIM,
                    nullptr, nullptr, nullptr };
        qkv_k<<<dim3(DIM / 128, S_IMG / 128, 3), blk, SMEM_BYTES>>>(
            x, pi, DIM, DIM, DIM, DIM, 1.f);

        Ptr3 pe = { waq, wak, wav, q, k, v, baq, bak, bav };
        qkv_k<<<dim3(DIM / 128, S_TXT / 128, 3), blk, SMEM_BYTES>>>(
            ehs, pe, DIM, DIM, DIM, DIM, 1.f);
    }

    // ---- RMSNorm + RoPE on q, k
    {
        dim3 g((S_TOT * HEADS) / 4);
        rmsnorm_rope_k<<<g, dim3(128)>>>(q, naqw, nqw, rcos, rsin);
        rmsnorm_rope_k<<<g, dim3(128)>>>(k, nakw, nkw, rcos, rsin);
    }

    // ---- scores = scale * Q Kᵀ  (batched over heads)
    gemm_bf16_k<true><<<dim3(S_TOT / 128, S_TOT / 128, HEADS), blk, SMEM_BYTES>>>(
        q, k, nullptr, sc, HDIM, DIM, DIM, S_TOT, HDIM, HDIM, HS, QK_SCALE);

    // ---- softmax over k
    softmax_k<<<dim3(HEADS * S_TOT), blk>>>(sc);

    // ---- O = P V  (batched over heads)
    gemm_bf16_k<false><<<dim3(HDIM / 128, S_TOT / 128, HEADS), blk, SMEM_BYTES>>>(
        sc, v, nullptr, o, S_TOT, S_TOT, DIM, DIM, HS, HDIM, HDIM, 1.f);

    // ---- output projections: img part first in d_out, then enc part
    gemm_bf16_k<true><<<dim3(DIM / 128, S_IMG / 128, 1), blk, SMEM_BYTES>>>(
        o + (size_t)S_TXT * DIM, wo, bo, out, DIM, DIM, DIM, DIM, 0, 0, 0, 1.f);
    gemm_bf16_k<true><<<dim3(DIM / 128, S_TXT / 128, 1), blk, SMEM_BYTES>>>(
        o, wao, bao, out + (size_t)S_IMG * DIM, DIM, DIM, DIM, DIM, 0, 0, 0, 1.f);
}